// round 3
// baseline (speedup 1.0000x reference)
#include <cuda_runtime.h>

#define NN 50000
#define NE 500000
#define D 128
#define TDIM 32
#define EDIM 160
#define TE 128       // edges per block (edge kernel, mma)
#define SA 164       // attr tile smem stride (words)
#define SB 136       // We tile smem stride (words)
#define SE 132       // e-result smem stride (words)
#define TNODE 64     // nodes per block (proj kernel)

// ---- scratch (no cudaMalloc allowed) ----
__device__ float g_q[NN * D];
__device__ float g_k[NN * D];
__device__ float g_v[NN * D];
__device__ float g_agg[NN * D];
__device__ float g_sum[NN * 2];
__device__ int   g_idx64;

// ---- helpers ----
__device__ __forceinline__ unsigned to_tf32(float f) {
    unsigned r;
    asm("cvt.rna.tf32.f32 %0, %1;" : "=r"(r) : "f"(f));
    return r;
}
__device__ __forceinline__ unsigned long long dup2(float w) {
    unsigned long long d;
    asm("mov.b64 %0, {%1, %1};" : "=l"(d) : "r"(__float_as_uint(w)));
    return d;
}
__device__ __forceinline__ void fma2(unsigned long long& d,
                                     unsigned long long a, unsigned long long b) {
    asm("fma.rn.f32x2 %0, %1, %2, %0;" : "+l"(d) : "l"(a), "l"(b));
}
__device__ __forceinline__ float lo32(unsigned long long v) {
    return __uint_as_float((unsigned)(v & 0xffffffffu));
}
__device__ __forceinline__ float hi32(unsigned long long v) {
    return __uint_as_float((unsigned)(v >> 32));
}
__device__ __forceinline__ void red_v4(float* p, float a, float b, float c, float d) {
    asm volatile("red.global.add.v4.f32 [%0], {%1,%2,%3,%4};"
                 :: "l"(p), "f"(a), "f"(b), "f"(c), "f"(d) : "memory");
}
__device__ __forceinline__ void red_1(float* p, float a) {
    asm volatile("red.global.add.f32 [%0], %1;" :: "l"(p), "f"(a) : "memory");
}
__device__ __forceinline__ void mma_tf32(float* c, const unsigned* a,
                                         unsigned b0, unsigned b1) {
    asm volatile(
        "mma.sync.aligned.m16n8k8.row.col.f32.tf32.tf32.f32 "
        "{%0,%1,%2,%3}, {%4,%5,%6,%7}, {%8,%9}, {%0,%1,%2,%3};"
        : "+f"(c[0]), "+f"(c[1]), "+f"(c[2]), "+f"(c[3])
        : "r"(a[0]), "r"(a[1]), "r"(a[2]), "r"(a[3]), "r"(b0), "r"(b1));
}

// Detect int64 vs int32 edge_index.
__global__ void detect_kernel(const long long* __restrict__ ei) {
    if (threadIdx.x == 0 && blockIdx.x == 0) {
        bool ok = true;
        #pragma unroll
        for (int i = 0; i < 16; i++) {
            long long v = ei[i];
            if (v < 0 || v >= NN) ok = false;
        }
        g_idx64 = ok ? 1 : 0;
    }
}

__global__ void zero_kernel() {
    int idx = blockIdx.x * blockDim.x + threadIdx.x;
    if (idx < NN * D) g_agg[idx] = 0.0f;
    if (idx < NN * 2) g_sum[idx] = 0.0f;
}

// ---- proj: q,k,v,skip = x @ W + b (FFMA2 tiled, unchanged from R2) ----
__global__ __launch_bounds__(256) void proj_kernel(
    const float* __restrict__ x,
    const float* __restrict__ Wq, const float* __restrict__ bq,
    const float* __restrict__ Wk, const float* __restrict__ bk,
    const float* __restrict__ Wv, const float* __restrict__ bv,
    const float* __restrict__ Ws, const float* __restrict__ bs,
    float* __restrict__ out)
{
    __shared__ float xT[D][TNODE];
    const int tid = threadIdx.x;
    const int n0  = blockIdx.x * TNODE;

    for (int i = tid; i < 32 * TNODE; i += 256) {
        const int q = i >> 6, e = i & 63;
        float4 m = make_float4(0, 0, 0, 0);
        if (n0 + e < NN) m = __ldg((const float4*)(x + (size_t)(n0 + e) * D) + q);
        xT[4 * q + 0][e] = m.x; xT[4 * q + 1][e] = m.y;
        xT[4 * q + 2][e] = m.z; xT[4 * q + 3][e] = m.w;
    }
    __syncthreads();

    const int lane = tid & 31, w = tid >> 5;
    const float* Wlist[4] = {Wq, Wk, Wv, Ws};
    const float* blist[4] = {bq, bk, bv, bs};
    float*       dlist[4] = {g_q, g_k, g_v, out};

    #pragma unroll
    for (int m = 0; m < 4; m++) {
        const float4* W4 = (const float4*)Wlist[m];
        unsigned long long acc[4][4];
        #pragma unroll
        for (int i = 0; i < 4; i++)
            #pragma unroll
            for (int j = 0; j < 4; j++) acc[i][j] = 0ull;

        #pragma unroll 4
        for (int k = 0; k < D; k++) {
            const double2* ap = (const double2*)(&xT[k][w * 8]);
            double2 p0 = ap[0], p1 = ap[1];
            unsigned long long a0 = __double_as_longlong(p0.x);
            unsigned long long a1 = __double_as_longlong(p0.y);
            unsigned long long a2 = __double_as_longlong(p1.x);
            unsigned long long a3 = __double_as_longlong(p1.y);
            const float4 wv = __ldg(W4 + k * 32 + lane);
            unsigned long long w0 = dup2(wv.x), w1 = dup2(wv.y),
                               w2 = dup2(wv.z), w3 = dup2(wv.w);
            fma2(acc[0][0], a0, w0); fma2(acc[0][1], a0, w1);
            fma2(acc[0][2], a0, w2); fma2(acc[0][3], a0, w3);
            fma2(acc[1][0], a1, w0); fma2(acc[1][1], a1, w1);
            fma2(acc[1][2], a1, w2); fma2(acc[1][3], a1, w3);
            fma2(acc[2][0], a2, w0); fma2(acc[2][1], a2, w1);
            fma2(acc[2][2], a2, w2); fma2(acc[2][3], a2, w3);
            fma2(acc[3][0], a3, w0); fma2(acc[3][1], a3, w1);
            fma2(acc[3][2], a3, w2); fma2(acc[3][3], a3, w3);
        }

        const float4 bb = __ldg((const float4*)blist[m] + lane);
        float* dst = dlist[m];
        #pragma unroll
        for (int i = 0; i < 4; i++) {
            const int nA = n0 + w * 8 + i * 2;
            if (nA < NN) {
                float4 o = make_float4(lo32(acc[i][0]) + bb.x, lo32(acc[i][1]) + bb.y,
                                       lo32(acc[i][2]) + bb.z, lo32(acc[i][3]) + bb.w);
                *(float4*)(dst + (size_t)nA * D + lane * 4) = o;
            }
            if (nA + 1 < NN) {
                float4 o = make_float4(hi32(acc[i][0]) + bb.x, hi32(acc[i][1]) + bb.y,
                                       hi32(acc[i][2]) + bb.z, hi32(acc[i][3]) + bb.w);
                *(float4*)(dst + (size_t)(nA + 1) * D + lane * 4) = o;
            }
        }
    }
}

// ---- edge: attr build + tf32 tensor-core GEMM (attr@We) + attention + scatter ----
__global__ __launch_bounds__(256) void edge_kernel(
    const void*  __restrict__ ei_raw,
    const float* __restrict__ last_update,
    const float* __restrict__ t,
    const float* __restrict__ msg,
    const float* __restrict__ time_w,
    const float* __restrict__ time_b,
    const float* __restrict__ We)
{
    extern __shared__ unsigned smemu[];
    unsigned* sA = smemu;                 // [TE][SA] tf32 attr tile
    unsigned* sB = smemu + TE * SA;       // [EDIM][SB] tf32 We
    float*    eS = (float*)smemu;         // [TE][SE] result, overlays sA after GEMM

    __shared__ int   s_src[TE], s_dst[TE];
    __shared__ float s_rel[TE];

    const int tid = threadIdx.x;
    const int e0  = blockIdx.x * TE;

    // phase 1: indices + rel time
    if (tid < TE) {
        const int eg = e0 + tid;
        int src = 0, dst = 0; float rel = 0.f;
        if (eg < NE) {
            if (g_idx64) {
                const long long* p = (const long long*)ei_raw;
                src = (int)__ldg(p + eg); dst = (int)__ldg(p + NE + eg);
            } else {
                const int* p = (const int*)ei_raw;
                src = __ldg(p + eg); dst = __ldg(p + NE + eg);
            }
            rel = __ldg(last_update + src) - __ldg(t + eg);
        }
        s_src[tid] = src; s_dst[tid] = dst; s_rel[tid] = rel;
    }
    __syncthreads();

    // phase 2: stage We (tf32), time rows, msg rows
    for (int i = tid; i < EDIM * 32; i += 256) {          // We: 160 x 128
        const int k = i >> 5, q = i & 31;
        const float4 wv = __ldg((const float4*)We + k * 32 + q);
        unsigned* p = sB + k * SB + 4 * q;
        p[0] = to_tf32(wv.x); p[1] = to_tf32(wv.y);
        p[2] = to_tf32(wv.z); p[3] = to_tf32(wv.w);
    }
    for (int i = tid; i < TE * TDIM; i += 256) {          // time encode rows
        const int e = i >> 5, k = i & 31;
        float v = 0.f;
        if (e0 + e < NE)
            v = cosf(s_rel[e] * __ldg(time_w + k) + __ldg(time_b + k));
        sA[e * SA + k] = to_tf32(v);
    }
    for (int i = tid; i < TE * 32; i += 256) {            // msg rows
        const int e = i >> 5, q = i & 31;
        float4 m = make_float4(0, 0, 0, 0);
        if (e0 + e < NE) m = __ldg((const float4*)(msg + (size_t)(e0 + e) * D) + q);
        unsigned* p = sA + e * SA + TDIM + 4 * q;
        p[0] = to_tf32(m.x); p[1] = to_tf32(m.y);
        p[2] = to_tf32(m.z); p[3] = to_tf32(m.w);
    }
    __syncthreads();

    // phase 3: GEMM. 8 warps in 4(M) x 2(N); warp tile 32 x 64.
    const int wid = tid >> 5, lane = tid & 31;
    const int g = lane >> 2, tg = lane & 3;
    const int wm = wid & 3, wn = wid >> 2;

    float acc[2][8][4];
    #pragma unroll
    for (int mi = 0; mi < 2; mi++)
        #pragma unroll
        for (int ni = 0; ni < 8; ni++)
            #pragma unroll
            for (int r = 0; r < 4; r++) acc[mi][ni][r] = 0.f;

    const unsigned* Abase = sA + (wm * 32 + g) * SA + tg;
    const unsigned* Bbase = sB + tg * SB + wn * 64 + g;

    #pragma unroll 2
    for (int ks = 0; ks < EDIM / 8; ks++) {
        const int k0 = ks * 8;
        unsigned a[2][4];
        #pragma unroll
        for (int mi = 0; mi < 2; mi++) {
            const unsigned* ap = Abase + mi * 16 * SA + k0;
            a[mi][0] = ap[0];
            a[mi][1] = ap[8 * SA];
            a[mi][2] = ap[4];
            a[mi][3] = ap[8 * SA + 4];
        }
        const unsigned* bp = Bbase + k0 * SB;
        #pragma unroll
        for (int ni = 0; ni < 8; ni++) {
            const unsigned b0 = bp[ni * 8];
            const unsigned b1 = bp[4 * SB + ni * 8];
            mma_tf32(acc[0][ni], a[0], b0, b1);
            mma_tf32(acc[1][ni], a[1], b0, b1);
        }
    }
    __syncthreads();   // everyone done reading sA

    // phase 4: accumulators -> smem e-matrix
    #pragma unroll
    for (int mi = 0; mi < 2; mi++) {
        const int r0 = wm * 32 + mi * 16 + g;
        #pragma unroll
        for (int ni = 0; ni < 8; ni++) {
            const int c = wn * 64 + ni * 8 + 2 * tg;
            *(float2*)&eS[r0 * SE + c]       = make_float2(acc[mi][ni][0], acc[mi][ni][1]);
            *(float2*)&eS[(r0 + 8) * SE + c] = make_float2(acc[mi][ni][2], acc[mi][ni][3]);
        }
    }
    __syncthreads();

    // phase 5: attention epilogue. warp handles 16 edges; lane owns 4 cols.
    const int col = lane * 4;
    #pragma unroll 4
    for (int ii = 0; ii < 16; ii++) {
        const int eL = wid * 16 + ii;
        const int eg = e0 + eL;
        if (eg < NE) {
            const int src = s_src[eL], dst = s_dst[eL];
            const float4 ev = *(const float4*)&eS[eL * SE + col];
            const float4 qi = *(const float4*)(g_q + (size_t)dst * D + col);
            float4 kj = *(const float4*)(g_k + (size_t)src * D + col);
            float4 vj = *(const float4*)(g_v + (size_t)src * D + col);
            kj.x += ev.x; kj.y += ev.y; kj.z += ev.z; kj.w += ev.w;
            vj.x += ev.x; vj.y += ev.y; vj.z += ev.z; vj.w += ev.w;

            float p = qi.x * kj.x + qi.y * kj.y + qi.z * kj.z + qi.w * kj.w;
            p += __shfl_xor_sync(0xffffffffu, p, 1);
            p += __shfl_xor_sync(0xffffffffu, p, 2);
            p += __shfl_xor_sync(0xffffffffu, p, 4);
            p += __shfl_xor_sync(0xffffffffu, p, 8);
            const float ex = expf(p * 0.125f);   // 1/sqrt(64); exact softmax w/o max-sub

            red_v4(g_agg + (size_t)dst * D + col,
                   ex * vj.x, ex * vj.y, ex * vj.z, ex * vj.w);
            if ((lane & 15) == 0)
                red_1(&g_sum[dst * 2 + (lane >> 4)], ex);
        }
    }
}

__global__ void finalize_kernel(float* __restrict__ out) {
    int idx = blockIdx.x * blockDim.x + threadIdx.x;
    if (idx >= NN * 32) return;
    const int n = idx >> 5;
    const int h = (idx & 31) >> 4;
    const float inv = 1.0f / (g_sum[n * 2 + h] + 1e-16f);
    float4 a = ((const float4*)g_agg)[idx];
    float4 o = ((float4*)out)[idx];
    o.x += a.x * inv; o.y += a.y * inv; o.z += a.z * inv; o.w += a.w * inv;
    ((float4*)out)[idx] = o;
}

extern "C" void kernel_launch(void* const* d_in, const int* in_sizes, int n_in,
                              void* d_out, int out_size) {
    const float* x           = (const float*)d_in[0];
    const float* last_update = (const float*)d_in[1];
    const void*  ei          = d_in[2];
    const float* t           = (const float*)d_in[3];
    const float* msg         = (const float*)d_in[4];
    const float* time_w      = (const float*)d_in[5];
    const float* time_b      = (const float*)d_in[6];
    const float* Wq          = (const float*)d_in[7];
    const float* bq          = (const float*)d_in[8];
    const float* Wk          = (const float*)d_in[9];
    const float* bk          = (const float*)d_in[10];
    const float* Wv          = (const float*)d_in[11];
    const float* bv          = (const float*)d_in[12];
    const float* We          = (const float*)d_in[13];
    const float* Ws          = (const float*)d_in[14];
    const float* bs          = (const float*)d_in[15];
    float* out = (float*)d_out;

    const int smem_edge = (TE * SA + EDIM * SB) * 4;   // 171,008 bytes
    static int configured = 0;
    if (!configured) {
        cudaFuncSetAttribute(edge_kernel,
                             cudaFuncAttributeMaxDynamicSharedMemorySize, smem_edge);
        configured = 1;
    }

    detect_kernel<<<1, 32>>>((const long long*)ei);
    zero_kernel<<<(NN * D + 255) / 256, 256>>>();
    proj_kernel<<<(NN + TNODE - 1) / TNODE, 256>>>(x, Wq, bq, Wk, bk, Wv, bv, Ws, bs, out);
    edge_kernel<<<(NE + TE - 1) / TE, 256, smem_edge>>>(ei, last_update, t, msg,
                                                        time_w, time_b, We);
    finalize_kernel<<<(NN * 32 + 255) / 256, 256>>>(out);
}

// round 4
// speedup vs baseline: 1.4535x; 1.4535x over previous
#include <cuda_runtime.h>

#define NN 50000
#define NE 500000
#define D 128
#define TDIM 32
#define EDIM 160
#define TE 128       // edges per block (E1 GEMM)
#define SA 164       // attr tile smem stride (words)
#define TNODE 64     // nodes per block (proj kernel)

// ---- scratch (no cudaMalloc allowed) ----
__device__ float g_q[NN * D];
__device__ float g_k[NN * D];
__device__ float g_v[NN * D];
__device__ float g_agg[NN * D];
__device__ float g_sum[NN * 2];
__device__ float g_e[(size_t)NE * D];   // 256MB edge projection scratch
__device__ int   g_idx64;

// ---- helpers ----
__device__ __forceinline__ unsigned to_tf32(float f) {
    unsigned r;
    asm("cvt.rna.tf32.f32 %0, %1;" : "=r"(r) : "f"(f));
    return r;
}
__device__ __forceinline__ unsigned long long dup2(float w) {
    unsigned long long d;
    asm("mov.b64 %0, {%1, %1};" : "=l"(d) : "r"(__float_as_uint(w)));
    return d;
}
__device__ __forceinline__ void fma2(unsigned long long& d,
                                     unsigned long long a, unsigned long long b) {
    asm("fma.rn.f32x2 %0, %1, %2, %0;" : "+l"(d) : "l"(a), "l"(b));
}
__device__ __forceinline__ float lo32(unsigned long long v) {
    return __uint_as_float((unsigned)(v & 0xffffffffu));
}
__device__ __forceinline__ float hi32(unsigned long long v) {
    return __uint_as_float((unsigned)(v >> 32));
}
__device__ __forceinline__ void red_v4(float* p, float a, float b, float c, float d) {
    asm volatile("red.global.add.v4.f32 [%0], {%1,%2,%3,%4};"
                 :: "l"(p), "f"(a), "f"(b), "f"(c), "f"(d) : "memory");
}
__device__ __forceinline__ void red_1(float* p, float a) {
    asm volatile("red.global.add.f32 [%0], %1;" :: "l"(p), "f"(a) : "memory");
}
__device__ __forceinline__ void mma_tf32(float* c, const unsigned* a,
                                         unsigned b0, unsigned b1) {
    asm volatile(
        "mma.sync.aligned.m16n8k8.row.col.f32.tf32.tf32.f32 "
        "{%0,%1,%2,%3}, {%4,%5,%6,%7}, {%8,%9}, {%0,%1,%2,%3};"
        : "+f"(c[0]), "+f"(c[1]), "+f"(c[2]), "+f"(c[3])
        : "r"(a[0]), "r"(a[1]), "r"(a[2]), "r"(a[3]), "r"(b0), "r"(b1));
}

// Detect int64 vs int32 edge_index.
__global__ void detect_kernel(const long long* __restrict__ ei) {
    if (threadIdx.x == 0 && blockIdx.x == 0) {
        bool ok = true;
        #pragma unroll
        for (int i = 0; i < 16; i++) {
            long long v = ei[i];
            if (v < 0 || v >= NN) ok = false;
        }
        g_idx64 = ok ? 1 : 0;
    }
}

__global__ void zero_kernel() {
    int idx = blockIdx.x * blockDim.x + threadIdx.x;
    if (idx < NN * D) g_agg[idx] = 0.0f;
    if (idx < NN * 2) g_sum[idx] = 0.0f;
}

// ---- proj: q,k,v,skip = x @ W + b (FFMA2 tiled, unchanged) ----
__global__ __launch_bounds__(256) void proj_kernel(
    const float* __restrict__ x,
    const float* __restrict__ Wq, const float* __restrict__ bq,
    const float* __restrict__ Wk, const float* __restrict__ bk,
    const float* __restrict__ Wv, const float* __restrict__ bv,
    const float* __restrict__ Ws, const float* __restrict__ bs,
    float* __restrict__ out)
{
    __shared__ float xT[D][TNODE];
    const int tid = threadIdx.x;
    const int n0  = blockIdx.x * TNODE;

    for (int i = tid; i < 32 * TNODE; i += 256) {
        const int q = i >> 6, e = i & 63;
        float4 m = make_float4(0, 0, 0, 0);
        if (n0 + e < NN) m = __ldg((const float4*)(x + (size_t)(n0 + e) * D) + q);
        xT[4 * q + 0][e] = m.x; xT[4 * q + 1][e] = m.y;
        xT[4 * q + 2][e] = m.z; xT[4 * q + 3][e] = m.w;
    }
    __syncthreads();

    const int lane = tid & 31, w = tid >> 5;
    const float* Wlist[4] = {Wq, Wk, Wv, Ws};
    const float* blist[4] = {bq, bk, bv, bs};
    float*       dlist[4] = {g_q, g_k, g_v, out};

    #pragma unroll
    for (int m = 0; m < 4; m++) {
        const float4* W4 = (const float4*)Wlist[m];
        unsigned long long acc[4][4];
        #pragma unroll
        for (int i = 0; i < 4; i++)
            #pragma unroll
            for (int j = 0; j < 4; j++) acc[i][j] = 0ull;

        #pragma unroll 4
        for (int k = 0; k < D; k++) {
            const double2* ap = (const double2*)(&xT[k][w * 8]);
            double2 p0 = ap[0], p1 = ap[1];
            unsigned long long a0 = __double_as_longlong(p0.x);
            unsigned long long a1 = __double_as_longlong(p0.y);
            unsigned long long a2 = __double_as_longlong(p1.x);
            unsigned long long a3 = __double_as_longlong(p1.y);
            const float4 wv = __ldg(W4 + k * 32 + lane);
            unsigned long long w0 = dup2(wv.x), w1 = dup2(wv.y),
                               w2 = dup2(wv.z), w3 = dup2(wv.w);
            fma2(acc[0][0], a0, w0); fma2(acc[0][1], a0, w1);
            fma2(acc[0][2], a0, w2); fma2(acc[0][3], a0, w3);
            fma2(acc[1][0], a1, w0); fma2(acc[1][1], a1, w1);
            fma2(acc[1][2], a1, w2); fma2(acc[1][3], a1, w3);
            fma2(acc[2][0], a2, w0); fma2(acc[2][1], a2, w1);
            fma2(acc[2][2], a2, w2); fma2(acc[2][3], a2, w3);
            fma2(acc[3][0], a3, w0); fma2(acc[3][1], a3, w1);
            fma2(acc[3][2], a3, w2); fma2(acc[3][3], a3, w3);
        }

        const float4 bb = __ldg((const float4*)blist[m] + lane);
        float* dst = dlist[m];
        #pragma unroll
        for (int i = 0; i < 4; i++) {
            const int nA = n0 + w * 8 + i * 2;
            if (nA < NN) {
                float4 o = make_float4(lo32(acc[i][0]) + bb.x, lo32(acc[i][1]) + bb.y,
                                       lo32(acc[i][2]) + bb.z, lo32(acc[i][3]) + bb.w);
                *(float4*)(dst + (size_t)nA * D + lane * 4) = o;
            }
            if (nA + 1 < NN) {
                float4 o = make_float4(hi32(acc[i][0]) + bb.x, hi32(acc[i][1]) + bb.y,
                                       hi32(acc[i][2]) + bb.z, hi32(acc[i][3]) + bb.w);
                *(float4*)(dst + (size_t)(nA + 1) * D + lane * 4) = o;
            }
        }
    }
}

// ---- E1: e = attr @ We (tf32 mma, B fragments straight from gmem) ----
__global__ __launch_bounds__(256, 2) void egemm_kernel(
    const void*  __restrict__ ei_raw,
    const float* __restrict__ last_update,
    const float* __restrict__ t,
    const float* __restrict__ msg,
    const float* __restrict__ time_w,
    const float* __restrict__ time_b,
    const float* __restrict__ We)
{
    extern __shared__ unsigned sA[];    // [TE][SA] tf32 attr tile (84KB)
    __shared__ float s_rel[TE];

    const int tid = threadIdx.x;
    const int e0  = blockIdx.x * TE;

    // phase 1: rel time per edge
    if (tid < TE) {
        const int eg = e0 + tid;
        float rel = 0.f;
        if (eg < NE) {
            int src;
            if (g_idx64) src = (int)__ldg((const long long*)ei_raw + eg);
            else         src = __ldg((const int*)ei_raw + eg);
            rel = __ldg(last_update + src) - __ldg(t + eg);
        }
        s_rel[tid] = rel;
    }
    __syncthreads();

    // phase 2: build attr tile (tf32)
    for (int i = tid; i < TE * TDIM; i += 256) {          // time-encode cols [0,32)
        const int e = i >> 5, k = i & 31;
        float v = 0.f;
        if (e0 + e < NE)
            v = cosf(s_rel[e] * __ldg(time_w + k) + __ldg(time_b + k));
        sA[e * SA + k] = to_tf32(v);
    }
    for (int i = tid; i < TE * 32; i += 256) {            // msg cols [32,160)
        const int e = i >> 5, q = i & 31;
        float4 m = make_float4(0, 0, 0, 0);
        if (e0 + e < NE) m = __ldg((const float4*)(msg + (size_t)(e0 + e) * D) + q);
        unsigned* p = sA + e * SA + TDIM + 4 * q;
        p[0] = to_tf32(m.x); p[1] = to_tf32(m.y);
        p[2] = to_tf32(m.z); p[3] = to_tf32(m.w);
    }
    __syncthreads();

    // phase 3: GEMM. 8 warps: 4(M) x 2(N); warp tile 32x64.
    const int wid = tid >> 5, lane = tid & 31;
    const int g = lane >> 2, tg = lane & 3;
    const int wm = wid & 3, wn = wid >> 2;

    float acc[2][8][4];
    #pragma unroll
    for (int mi = 0; mi < 2; mi++)
        #pragma unroll
        for (int ni = 0; ni < 8; ni++)
            #pragma unroll
            for (int r = 0; r < 4; r++) acc[mi][ni][r] = 0.f;

    const unsigned* Abase = sA + (wm * 32 + g) * SA + tg;
    const float*    Bbase = We + tg * D + wn * 64 + g;    // [k=tg][col]

    #pragma unroll 2
    for (int ks = 0; ks < EDIM / 8; ks++) {
        const int k0 = ks * 8;
        unsigned a[2][4];
        #pragma unroll
        for (int mi = 0; mi < 2; mi++) {
            const unsigned* ap = Abase + mi * 16 * SA + k0;
            a[mi][0] = ap[0];
            a[mi][1] = ap[8 * SA];
            a[mi][2] = ap[4];
            a[mi][3] = ap[8 * SA + 4];
        }
        const float* bp = Bbase + k0 * D;
        #pragma unroll
        for (int ni = 0; ni < 8; ni++) {
            const unsigned b0 = to_tf32(__ldg(bp + ni * 8));
            const unsigned b1 = to_tf32(__ldg(bp + 4 * D + ni * 8));
            mma_tf32(acc[0][ni], a[0], b0, b1);
            mma_tf32(acc[1][ni], a[1], b0, b1);
        }
    }

    // phase 4: write e tile to gmem
    #pragma unroll
    for (int mi = 0; mi < 2; mi++) {
        const int r0 = wm * 32 + mi * 16 + g;
        #pragma unroll
        for (int ni = 0; ni < 8; ni++) {
            const int c = wn * 64 + ni * 8 + 2 * tg;
            if (e0 + r0 < NE)
                *(float2*)(g_e + (size_t)(e0 + r0) * D + c) =
                    make_float2(acc[mi][ni][0], acc[mi][ni][1]);
            if (e0 + r0 + 8 < NE)
                *(float2*)(g_e + (size_t)(e0 + r0 + 8) * D + c) =
                    make_float2(acc[mi][ni][2], acc[mi][ni][3]);
        }
    }
}

// ---- E2: attention epilogue. Warp handles 8 edges; lane owns 4 cols. ----
__global__ __launch_bounds__(256) void epilogue_kernel(
    const void* __restrict__ ei_raw)
{
    const int tid  = threadIdx.x;
    const int w    = tid >> 5, lane = tid & 31;
    const int col  = lane * 4;
    const int e0   = blockIdx.x * 64 + w * 8;

    #pragma unroll 2
    for (int ii = 0; ii < 8; ii++) {
        const int eg = e0 + ii;
        if (eg < NE) {
            int src, dst;
            if (g_idx64) {
                const long long* p = (const long long*)ei_raw;
                src = (int)__ldg(p + eg); dst = (int)__ldg(p + NE + eg);
            } else {
                const int* p = (const int*)ei_raw;
                src = __ldg(p + eg); dst = __ldg(p + NE + eg);
            }
            const float4 ev = __ldg((const float4*)(g_e + (size_t)eg * D) + lane);
            const float4 qi = *(const float4*)(g_q + (size_t)dst * D + col);
            float4 kj = *(const float4*)(g_k + (size_t)src * D + col);
            float4 vj = *(const float4*)(g_v + (size_t)src * D + col);
            kj.x += ev.x; kj.y += ev.y; kj.z += ev.z; kj.w += ev.w;
            vj.x += ev.x; vj.y += ev.y; vj.z += ev.z; vj.w += ev.w;

            float p = qi.x * kj.x + qi.y * kj.y + qi.z * kj.z + qi.w * kj.w;
            p += __shfl_xor_sync(0xffffffffu, p, 1);
            p += __shfl_xor_sync(0xffffffffu, p, 2);
            p += __shfl_xor_sync(0xffffffffu, p, 4);
            p += __shfl_xor_sync(0xffffffffu, p, 8);
            const float ex = expf(p * 0.125f);   // 1/sqrt(64); exact softmax w/o max-sub

            red_v4(g_agg + (size_t)dst * D + col,
                   ex * vj.x, ex * vj.y, ex * vj.z, ex * vj.w);
            if ((lane & 15) == 0)
                red_1(&g_sum[dst * 2 + (lane >> 4)], ex);
        }
    }
}

__global__ void finalize_kernel(float* __restrict__ out) {
    int idx = blockIdx.x * blockDim.x + threadIdx.x;
    if (idx >= NN * 32) return;
    const int n = idx >> 5;
    const int h = (idx & 31) >> 4;
    const float inv = 1.0f / (g_sum[n * 2 + h] + 1e-16f);
    float4 a = ((const float4*)g_agg)[idx];
    float4 o = ((float4*)out)[idx];
    o.x += a.x * inv; o.y += a.y * inv; o.z += a.z * inv; o.w += a.w * inv;
    ((float4*)out)[idx] = o;
}

extern "C" void kernel_launch(void* const* d_in, const int* in_sizes, int n_in,
                              void* d_out, int out_size) {
    const float* x           = (const float*)d_in[0];
    const float* last_update = (const float*)d_in[1];
    const void*  ei          = d_in[2];
    const float* t           = (const float*)d_in[3];
    const float* msg         = (const float*)d_in[4];
    const float* time_w      = (const float*)d_in[5];
    const float* time_b      = (const float*)d_in[6];
    const float* Wq          = (const float*)d_in[7];
    const float* bq          = (const float*)d_in[8];
    const float* Wk          = (const float*)d_in[9];
    const float* bk          = (const float*)d_in[10];
    const float* Wv          = (const float*)d_in[11];
    const float* bv          = (const float*)d_in[12];
    const float* We          = (const float*)d_in[13];
    const float* Ws          = (const float*)d_in[14];
    const float* bs          = (const float*)d_in[15];
    float* out = (float*)d_out;

    const int smem_e1 = TE * SA * 4;   // 83,968 bytes
    static int configured = 0;
    if (!configured) {
        cudaFuncSetAttribute(egemm_kernel,
                             cudaFuncAttributeMaxDynamicSharedMemorySize, smem_e1);
        configured = 1;
    }

    detect_kernel<<<1, 32>>>((const long long*)ei);
    zero_kernel<<<(NN * D + 255) / 256, 256>>>();
    proj_kernel<<<(NN + TNODE - 1) / TNODE, 256>>>(x, Wq, bq, Wk, bk, Wv, bv, Ws, bs, out);
    egemm_kernel<<<(NE + TE - 1) / TE, 256, smem_e1>>>(ei, last_update, t, msg,
                                                       time_w, time_b, We);
    epilogue_kernel<<<(NE + 63) / 64, 256>>>(ei);
    finalize_kernel<<<(NN * 32 + 255) / 256, 256>>>(out);
}